// round 4
// baseline (speedup 1.0000x reference)
#include <cuda_runtime.h>
#include <math.h>

#define NB 32
#define NS 64
#define NE 512
#define NV 50257
#define NTOK (NB*NS)          // 2048
#define KSEL (NS/2)           // 32
#define EPS_ATK 0.4f
#define STD_MULT 3.0
#define COS_EPS 1e-8f

// ---------------- scratch (device globals; no allocation allowed) ----------
__device__ float  d_pert[NTOK*NE];   // perturbed embeddings (4 MB)
__device__ float  d_absg[NTOK];
__device__ int    d_mask[NTOK];
__device__ float  d_pinv[NTOK];
__device__ float  d_tinv[NV];
__device__ double d_sum;
__device__ double d_sumsq;
__device__ float  d_lb, d_ub;

// ---------------- reductions ----------------
__device__ __forceinline__ float blockReduceSumF(float v) {
    __shared__ float sh[32];
    int lane = threadIdx.x & 31, w = threadIdx.x >> 5;
    #pragma unroll
    for (int o = 16; o > 0; o >>= 1) v += __shfl_down_sync(0xffffffffu, v, o);
    if (lane == 0) sh[w] = v;
    __syncthreads();
    int nw = (blockDim.x + 31) >> 5;
    v = (threadIdx.x < nw) ? sh[threadIdx.x] : 0.f;
    if (w == 0) {
        #pragma unroll
        for (int o = 16; o > 0; o >>= 1) v += __shfl_down_sync(0xffffffffu, v, o);
    }
    __syncthreads();
    return v;  // valid in thread 0
}

// ---------------- K0: init per-launch scratch -----------------------------
__global__ void k_init() {
    d_sum = 0.0;
    d_sumsq = 0.0;
}

// ---------------- K1: per-token |grad| sum --------------------------------
__global__ void k_absgrad(const float* __restrict__ grad) {
    int t = blockIdx.x;
    const float* p = grad + (size_t)t * NE;
    float s = 0.f;
    for (int e = threadIdx.x; e < NE; e += blockDim.x) s += fabsf(p[e]);
    s = blockReduceSumF(s);
    if (threadIdx.x == 0) d_absg[t] = s;
}

// ---------------- K2: top-k mask per batch (rank count, stable ties) ------
__global__ void k_mask() {
    __shared__ float v[NS];
    int b = blockIdx.x, i = threadIdx.x;
    v[i] = d_absg[b * NS + i];
    __syncthreads();
    float me = v[i];
    int rank = 0;
    #pragma unroll 8
    for (int j = 0; j < NS; j++)
        rank += (v[j] > me) || (v[j] == me && j < i);
    d_mask[b * NS + i] = (rank < KSEL) ? 1 : 0;
}

// ---------------- K3: masked sum / sumsq (double accum) -------------------
__global__ void k_stats(const float* __restrict__ grad) {
    int t = blockIdx.x;
    if (!d_mask[t]) return;            // uniform per block
    const float* p = grad + (size_t)t * NE;
    double s = 0.0, s2 = 0.0;
    for (int e = threadIdx.x; e < NE; e += blockDim.x) {
        double x = (double)p[e];
        s += x; s2 += x * x;
    }
    __shared__ double sha[32], shb[32];
    int lane = threadIdx.x & 31, w = threadIdx.x >> 5;
    #pragma unroll
    for (int o = 16; o > 0; o >>= 1) {
        s  += __shfl_down_sync(0xffffffffu, s,  o);
        s2 += __shfl_down_sync(0xffffffffu, s2, o);
    }
    if (lane == 0) { sha[w] = s; shb[w] = s2; }
    __syncthreads();
    int nw = (blockDim.x + 31) >> 5;
    if (w == 0) {
        s  = (threadIdx.x < nw) ? sha[threadIdx.x] : 0.0;
        s2 = (threadIdx.x < nw) ? shb[threadIdx.x] : 0.0;
        #pragma unroll
        for (int o = 16; o > 0; o >>= 1) {
            s  += __shfl_down_sync(0xffffffffu, s,  o);
            s2 += __shfl_down_sync(0xffffffffu, s2, o);
        }
        if (lane == 0) {
            atomicAdd(&d_sum, s);
            atomicAdd(&d_sumsq, s2);
        }
    }
}

// ---------------- K4: finalize mean/std -> bounds -------------------------
__global__ void k_final() {
    double n = (double)NB * KSEL * NE;          // 524288 kept entries
    double mean = d_sum / n;
    double var = (d_sumsq - n * mean * mean) / (n - 1.0);
    double sd = sqrt(var);
    d_lb = (float)(mean - sd * STD_MULT);
    d_ub = (float)(mean + sd * STD_MULT);
}

// ---------------- K5: perturb + per-token norm ----------------------------
__global__ void k_perturb(const int* __restrict__ utt,
                          const float* __restrict__ emb,
                          const float* __restrict__ grad) {
    int t = blockIdx.x;
    int u = utt[t];
    int m = d_mask[t];
    float lb = d_lb, ub = d_ub;
    const float* erow = emb + (size_t)u * NE;
    const float* grow = grad + (size_t)t * NE;
    float* prow = d_pert + (size_t)t * NE;
    float acc = 0.f;
    for (int e = threadIdx.x; e < NE; e += blockDim.x) {
        float ev = erow[e];
        float dg = grow[e];
        float p = ev;
        if (m && (dg < lb || dg > ub))
            p += (dg > 0.f) ? EPS_ATK : ((dg < 0.f) ? -EPS_ATK : 0.f);
        prow[e] = p;
        acc += p * p;
    }
    acc = blockReduceSumF(acc);
    if (threadIdx.x == 0)
        d_pinv[t] = 1.f / fmaxf(sqrtf(acc), COS_EPS);
}

// ---------------- K6: vocab row norms -------------------------------------
__global__ void k_tnorm(const float* __restrict__ emb) {
    int v = blockIdx.x;
    const float* row = emb + (size_t)v * NE;
    float acc = 0.f;
    for (int e = threadIdx.x; e < NE; e += blockDim.x) {
        float x = row[e];
        acc += x * x;
    }
    acc = blockReduceSumF(acc);
    if (threadIdx.x == 0)
        d_tinv[v] = 1.f / fmaxf(sqrtf(acc), COS_EPS);
}

// ---------------- K7: SGEMM sim = pert @ emb^T, scaled by norms -----------
#define BM 128
#define BN 64
#define BKK 16
__global__ __launch_bounds__(256) void k_gemm(const float* __restrict__ emb,
                                              float* __restrict__ simOut) {
    __shared__ float As[BKK][BM];   // transposed A tile
    __shared__ float Bs[BKK][BN];   // transposed B tile
    int row0 = blockIdx.y * BM;
    int col0 = blockIdx.x * BN;
    int tid = threadIdx.x;
    int tx = tid & 15;              // 0..15 -> N
    int ty = tid >> 4;              // 0..15 -> M
    float acc[8][4];
    #pragma unroll
    for (int i = 0; i < 8; i++)
        #pragma unroll
        for (int j = 0; j < 4; j++) acc[i][j] = 0.f;

    const float* A = d_pert;
    for (int k0 = 0; k0 < NE; k0 += BKK) {
        // load A tile: 128 rows x 16 cols = 512 float4 slots, 2/thread
        #pragma unroll
        for (int i = 0; i < 2; i++) {
            int s = tid + i * 256;
            int r = s >> 2, c4 = s & 3;
            float4 v = *(const float4*)(A + (size_t)(row0 + r) * NE + k0 + c4 * 4);
            As[c4 * 4 + 0][r] = v.x;
            As[c4 * 4 + 1][r] = v.y;
            As[c4 * 4 + 2][r] = v.z;
            As[c4 * 4 + 3][r] = v.w;
        }
        // load B tile: 64 vocab rows x 16 cols = 256 float4 slots, 1/thread
        {
            int rn = tid >> 2, c4 = tid & 3;
            int vr = col0 + rn;
            float4 bv = make_float4(0.f, 0.f, 0.f, 0.f);
            if (vr < NV)
                bv = *(const float4*)(emb + (size_t)vr * NE + k0 + c4 * 4);
            Bs[c4 * 4 + 0][rn] = bv.x;
            Bs[c4 * 4 + 1][rn] = bv.y;
            Bs[c4 * 4 + 2][rn] = bv.z;
            Bs[c4 * 4 + 3][rn] = bv.w;
        }
        __syncthreads();
        #pragma unroll
        for (int k = 0; k < BKK; k++) {
            float4 a0 = *(const float4*)&As[k][ty * 8];
            float4 a1 = *(const float4*)&As[k][ty * 8 + 4];
            float4 bb = *(const float4*)&Bs[k][tx * 4];
            float av[8] = {a0.x, a0.y, a0.z, a0.w, a1.x, a1.y, a1.z, a1.w};
            float bv[4] = {bb.x, bb.y, bb.z, bb.w};
            #pragma unroll
            for (int i = 0; i < 8; i++)
                #pragma unroll
                for (int j = 0; j < 4; j++)
                    acc[i][j] = fmaf(av[i], bv[j], acc[i][j]);
        }
        __syncthreads();
    }
    // epilogue: scale by 1/(p_norm * t_norm), guard V edge
    #pragma unroll
    for (int i = 0; i < 8; i++) {
        int m = row0 + ty * 8 + i;
        float pi = d_pinv[m];
        float* orow = simOut + (size_t)m * NV;
        #pragma unroll
        for (int j = 0; j < 4; j++) {
            int n = col0 + tx * 4 + j;
            if (n < NV) orow[n] = acc[i][j] * pi * d_tinv[n];
        }
    }
}

// ---------------- K8: argmax over vocab per token (first-of-ties) ---------
__global__ void k_argmax(const float* __restrict__ sim, float* __restrict__ nnOut) {
    int t = blockIdx.x;
    const float* row = sim + (size_t)t * NV;
    float best = -1e30f;
    int bi = 0;
    for (int n = threadIdx.x; n < NV; n += blockDim.x) {
        float v = row[n];
        if (v > best) { best = v; bi = n; }   // strict > keeps first index
    }
    __shared__ float sv[256];
    __shared__ int si[256];
    sv[threadIdx.x] = best;
    si[threadIdx.x] = bi;
    __syncthreads();
    for (int stride = 128; stride > 0; stride >>= 1) {
        if (threadIdx.x < stride) {
            float ov = sv[threadIdx.x + stride];
            int oi = si[threadIdx.x + stride];
            if (ov > sv[threadIdx.x] ||
                (ov == sv[threadIdx.x] && oi < si[threadIdx.x])) {
                sv[threadIdx.x] = ov;
                si[threadIdx.x] = oi;
            }
        }
        __syncthreads();
    }
    if (threadIdx.x == 0) nnOut[t] = (float)si[0];
}

// ---------------- launch ---------------------------------------------------
extern "C" void kernel_launch(void* const* d_in, const int* in_sizes, int n_in,
                              void* d_out, int out_size) {
    const int* utt = (const int*)d_in[0];     // [B,S] int32
    const float* emb = (const float*)d_in[1]; // [V,E] fp32
    const float* grad = (const float*)d_in[2];// [B,S,E] fp32
    float* out = (float*)d_out;

    float* nnOut = nullptr;
    float* simOut = out;
    if (out_size == NTOK * (NV + 1)) {        // tuple order: nn_idx, then sim
        nnOut = out;
        simOut = out + NTOK;
    }

    k_init<<<1, 1>>>();
    k_absgrad<<<NTOK, 128>>>(grad);
    k_mask<<<NB, NS>>>();
    k_stats<<<NTOK, 256>>>(grad);
    k_final<<<1, 1>>>();
    k_perturb<<<NTOK, 128>>>(utt, emb, grad);
    k_tnorm<<<NV, 128>>>(emb);

    dim3 g((NV + BN - 1) / BN, NTOK / BM);
    k_gemm<<<g, 256>>>(emb, simOut);

    if (nnOut) k_argmax<<<NTOK, 256>>>(simOut, nnOut);
}

// round 6
// speedup vs baseline: 2.4522x; 2.4522x over previous
#include <cuda_runtime.h>
#include <cuda_bf16.h>
#include <math.h>
#include <stdint.h>

#define NB 32
#define NS 64
#define NE 512
#define NV 50257
#define NVP 50304             // NV padded to 128
#define NTOK (NB*NS)          // 2048
#define KSEL (NS/2)           // 32
#define EPS_ATK 0.4f
#define STD_MULT 3.0
#define COS_EPS 1e-8f

// GEMM tile config
#define TC_M 128
#define TC_N 128
#define KCH 64                // K per pipeline stage
#define NCHUNK (NE / KCH)     // 8
#define NBLK (NVP / TC_N)     // 393

// ---------------- scratch (device globals; no allocation allowed) ----------
__device__ __nv_bfloat16 d_pertHi[NTOK*NE];
__device__ __nv_bfloat16 d_pertLo[NTOK*NE];
__device__ __nv_bfloat16 d_embHi[NVP*NE];   // 51.5 MB
__device__ __nv_bfloat16 d_embLo[NVP*NE];   // 51.5 MB
__device__ float  d_absg[NTOK];
__device__ int    d_mask[NTOK];
__device__ float  d_pinv[NTOK];
__device__ float  d_tinv[NV];
__device__ double d_sum;
__device__ double d_sumsq;
__device__ float  d_lb, d_ub;
__device__ unsigned long long d_best[NTOK];

// ---------------- PTX helpers (baseline ISA only) ---------------------------
__device__ __forceinline__ uint32_t smem_u32(const void* p) {
    uint32_t a;
    asm("{ .reg .u64 t; cvta.to.shared.u64 t, %1; cvt.u32.u64 %0, t; }"
        : "=r"(a) : "l"(p));
    return a;
}
__device__ __forceinline__ void cp_async16(uint32_t dst, const void* src) {
    asm volatile("cp.async.cg.shared.global [%0], [%1], 16;"
                 :: "r"(dst), "l"(src) : "memory");
}
__device__ __forceinline__ void cp_commit() {
    asm volatile("cp.async.commit_group;" ::: "memory");
}
template<int N> __device__ __forceinline__ void cp_wait() {
    asm volatile("cp.async.wait_group %0;" :: "n"(N) : "memory");
}
__device__ __forceinline__ void ldmat4(uint32_t& r0, uint32_t& r1, uint32_t& r2,
                                       uint32_t& r3, uint32_t addr) {
    asm volatile("ldmatrix.sync.aligned.m8n8.x4.shared.b16 {%0,%1,%2,%3}, [%4];"
                 : "=r"(r0), "=r"(r1), "=r"(r2), "=r"(r3) : "r"(addr));
}
__device__ __forceinline__ void mma_bf16(float* d, const uint32_t* a, const uint32_t* b) {
    asm volatile(
        "mma.sync.aligned.m16n8k16.row.col.f32.bf16.bf16.f32 "
        "{%0,%1,%2,%3}, {%4,%5,%6,%7}, {%8,%9}, {%0,%1,%2,%3};"
        : "+f"(d[0]), "+f"(d[1]), "+f"(d[2]), "+f"(d[3])
        : "r"(a[0]), "r"(a[1]), "r"(a[2]), "r"(a[3]), "r"(b[0]), "r"(b[1]));
}

// argmax key: monotone float encoding, ~index for smaller-index-wins on ties
static __device__ __forceinline__ unsigned long long packKey(float v, int n) {
    unsigned u = __float_as_uint(v);
    u = (u & 0x80000000u) ? ~u : (u | 0x80000000u);
    return ((unsigned long long)u << 32) | (unsigned)(~n);
}

// ---------------- reductions ----------------
__device__ __forceinline__ float blockReduceSumF(float v) {
    __shared__ float sh[32];
    int lane = threadIdx.x & 31, w = threadIdx.x >> 5;
    #pragma unroll
    for (int o = 16; o > 0; o >>= 1) v += __shfl_down_sync(0xffffffffu, v, o);
    if (lane == 0) sh[w] = v;
    __syncthreads();
    int nw = (blockDim.x + 31) >> 5;
    v = (threadIdx.x < nw) ? sh[threadIdx.x] : 0.f;
    if (w == 0) {
        #pragma unroll
        for (int o = 16; o > 0; o >>= 1) v += __shfl_down_sync(0xffffffffu, v, o);
    }
    __syncthreads();
    return v;
}

// ---------------- K0: init ------------------------------------------------
__global__ void k_init() {
    int t = blockIdx.x * blockDim.x + threadIdx.x;
    if (t == 0) { d_sum = 0.0; d_sumsq = 0.0; }
    if (t < NTOK) d_best[t] = 0ull;
}

// ---------------- K1: per-token |grad| sum --------------------------------
__global__ void k_absgrad(const float* __restrict__ grad) {
    int t = blockIdx.x;
    const float* p = grad + (size_t)t * NE;
    float s = 0.f;
    for (int e = threadIdx.x; e < NE; e += blockDim.x) s += fabsf(p[e]);
    s = blockReduceSumF(s);
    if (threadIdx.x == 0) d_absg[t] = s;
}

// ---------------- K2: top-k mask (rank count, stable ties) ----------------
__global__ void k_mask() {
    __shared__ float v[NS];
    int b = blockIdx.x, i = threadIdx.x;
    v[i] = d_absg[b * NS + i];
    __syncthreads();
    float me = v[i];
    int rank = 0;
    #pragma unroll 8
    for (int j = 0; j < NS; j++)
        rank += (v[j] > me) || (v[j] == me && j < i);
    d_mask[b * NS + i] = (rank < KSEL) ? 1 : 0;
}

// ---------------- K3: masked sum / sumsq (double accum) -------------------
__global__ void k_stats(const float* __restrict__ grad) {
    int t = blockIdx.x;
    if (!d_mask[t]) return;
    const float* p = grad + (size_t)t * NE;
    double s = 0.0, s2 = 0.0;
    for (int e = threadIdx.x; e < NE; e += blockDim.x) {
        double x = (double)p[e];
        s += x; s2 += x * x;
    }
    __shared__ double sha[32], shb[32];
    int lane = threadIdx.x & 31, w = threadIdx.x >> 5;
    #pragma unroll
    for (int o = 16; o > 0; o >>= 1) {
        s  += __shfl_down_sync(0xffffffffu, s,  o);
        s2 += __shfl_down_sync(0xffffffffu, s2, o);
    }
    if (lane == 0) { sha[w] = s; shb[w] = s2; }
    __syncthreads();
    int nw = (blockDim.x + 31) >> 5;
    if (w == 0) {
        s  = (threadIdx.x < nw) ? sha[threadIdx.x] : 0.0;
        s2 = (threadIdx.x < nw) ? shb[threadIdx.x] : 0.0;
        #pragma unroll
        for (int o = 16; o > 0; o >>= 1) {
            s  += __shfl_down_sync(0xffffffffu, s,  o);
            s2 += __shfl_down_sync(0xffffffffu, s2, o);
        }
        if (lane == 0) { atomicAdd(&d_sum, s); atomicAdd(&d_sumsq, s2); }
    }
}

// ---------------- K4: finalize mean/std -> bounds -------------------------
__global__ void k_final() {
    double n = (double)NB * KSEL * NE;
    double mean = d_sum / n;
    double var = (d_sumsq - n * mean * mean) / (n - 1.0);
    double sd = sqrt(var);
    d_lb = (float)(mean - sd * STD_MULT);
    d_ub = (float)(mean + sd * STD_MULT);
}

// ---------------- K5: perturb + inv norm + bf16 hi/lo split ---------------
__global__ void k_perturb(const int* __restrict__ utt,
                          const float* __restrict__ emb,
                          const float* __restrict__ grad) {
    int t = blockIdx.x;
    int u = utt[t];
    int m = d_mask[t];
    float lb = d_lb, ub = d_ub;
    const float* erow = emb + (size_t)u * NE;
    const float* grow = grad + (size_t)t * NE;
    __nv_bfloat16* hrow = d_pertHi + (size_t)t * NE;
    __nv_bfloat16* lrow = d_pertLo + (size_t)t * NE;
    float acc = 0.f;
    for (int e = threadIdx.x; e < NE; e += blockDim.x) {
        float ev = erow[e];
        float dg = grow[e];
        float p = ev;
        if (m && (dg < lb || dg > ub))
            p += (dg > 0.f) ? EPS_ATK : ((dg < 0.f) ? -EPS_ATK : 0.f);
        __nv_bfloat16 h = __float2bfloat16(p);
        hrow[e] = h;
        lrow[e] = __float2bfloat16(p - __bfloat162float(h));
        acc += p * p;
    }
    acc = blockReduceSumF(acc);
    if (threadIdx.x == 0)
        d_pinv[t] = 1.f / fmaxf(sqrtf(acc), COS_EPS);
}

// ---------------- K6: vocab row inv norms ---------------------------------
__global__ void k_tnorm(const float* __restrict__ emb) {
    int v = blockIdx.x;
    const float* row = emb + (size_t)v * NE;
    float acc = 0.f;
    for (int e = threadIdx.x; e < NE; e += blockDim.x) {
        float x = row[e];
        acc += x * x;
    }
    acc = blockReduceSumF(acc);
    if (threadIdx.x == 0)
        d_tinv[v] = 1.f / fmaxf(sqrtf(acc), COS_EPS);
}

// ---------------- K6b: split emb into bf16 hi/lo planes (padded) ----------
__global__ void k_split_emb(const float* __restrict__ emb) {
    int i4 = blockIdx.x * blockDim.x + threadIdx.x;     // float4 index
    if (i4 >= NVP * NE / 4) return;
    int row = i4 >> 7;                                  // /(NE/4)
    float4 v = make_float4(0.f, 0.f, 0.f, 0.f);
    if (row < NV) v = __ldg((const float4*)emb + i4);
    __nv_bfloat16 h0 = __float2bfloat16(v.x), h1 = __float2bfloat16(v.y);
    __nv_bfloat16 h2 = __float2bfloat16(v.z), h3 = __float2bfloat16(v.w);
    __nv_bfloat16 l0 = __float2bfloat16(v.x - __bfloat162float(h0));
    __nv_bfloat16 l1 = __float2bfloat16(v.y - __bfloat162float(h1));
    __nv_bfloat16 l2 = __float2bfloat16(v.z - __bfloat162float(h2));
    __nv_bfloat16 l3 = __float2bfloat16(v.w - __bfloat162float(h3));
    uint2 hv, lv;
    hv.x = (uint32_t)__bfloat16_as_ushort(h0) | ((uint32_t)__bfloat16_as_ushort(h1) << 16);
    hv.y = (uint32_t)__bfloat16_as_ushort(h2) | ((uint32_t)__bfloat16_as_ushort(h3) << 16);
    lv.x = (uint32_t)__bfloat16_as_ushort(l0) | ((uint32_t)__bfloat16_as_ushort(l1) << 16);
    lv.y = (uint32_t)__bfloat16_as_ushort(l2) | ((uint32_t)__bfloat16_as_ushort(l3) << 16);
    ((uint2*)d_embHi)[i4] = hv;
    ((uint2*)d_embLo)[i4] = lv;
}

// ---------------- K7: HMMA bf16-split GEMM + fused epilogue ---------------
// sim = pert @ emb^T via hh + hl + lh passes (fp32 accum).
// SMEM per stage: aHi|aLo|bHi|bLo, each 128x64 bf16 = 16KB (XOR-swizzled).
#define STG_BYTES 65536
#define PLANE 16384

__global__ __launch_bounds__(256, 1) void k_gemm(float* __restrict__ simOut,
                                                 int doArgmax) {
    extern __shared__ char dsm[];
    __shared__ float s_tinv[TC_N];
    __shared__ float s_pinv[TC_M];

    const int tid = threadIdx.x;
    const int wid = tid >> 5;
    const int lane = tid & 31;
    const int warp_m = wid & 3;        // 4 row groups of 32
    const int warp_n = wid >> 2;       // 2 col groups of 64
    const int col0 = blockIdx.x * TC_N;
    const int row0 = blockIdx.y * TC_M;

    if (tid < TC_M) s_pinv[tid] = d_pinv[row0 + tid];
    if (tid < TC_N) {
        int c = col0 + tid;
        s_tinv[tid] = (c < NV) ? d_tinv[c] : 0.f;
    }

    const uint32_t smemBase = smem_u32(dsm);

    // ---- stage loader: 4 planes x 1024 chunks of 16B; 16 chunks/thread ----
    // chunk q in plane: r = q>>3 (row), c = q&7 (16B col); swizzle c ^= r&7
    auto loadStage = [&](int ch, int buf) {
        const int k0 = ch * KCH;
        uint32_t sb = smemBase + buf * STG_BYTES;
        #pragma unroll
        for (int i = 0; i < 4; i++) {
            int q = i * 256 + tid;
            int r = q >> 3, c = q & 7;
            uint32_t dst = sb + r * 128 + ((c ^ (r & 7)) << 4);
            const __nv_bfloat16* gA = d_pertHi + (size_t)(row0 + r) * NE + k0 + c * 8;
            cp_async16(dst, gA);
            cp_async16(dst + PLANE, d_pertLo + (size_t)(row0 + r) * NE + k0 + c * 8);
            cp_async16(dst + 2 * PLANE, d_embHi + (size_t)(col0 + r) * NE + k0 + c * 8);
            cp_async16(dst + 3 * PLANE, d_embLo + (size_t)(col0 + r) * NE + k0 + c * 8);
        }
    };

    float acc[2][8][4];
    #pragma unroll
    for (int i = 0; i < 2; i++)
        #pragma unroll
        for (int j = 0; j < 8; j++)
            #pragma unroll
            for (int k = 0; k < 4; k++) acc[i][j][k] = 0.f;

    // lane-derived ldmatrix addressing constants
    const int aRowIn = lane & 15;                // row within m16 tile
    const int aSel = lane >> 4;                  // k8 selector
    const int bRowIn = (lane & 7) + ((lane >> 4) << 3);  // n within n16 pair
    const int bSel = (lane >> 3) & 1;            // k8 selector

    loadStage(0, 0); cp_commit();
    loadStage(1, 1); cp_commit();

    for (int ch = 0; ch < NCHUNK; ch++) {
        if (ch < NCHUNK - 1) cp_wait<1>(); else cp_wait<0>();
        __syncthreads();
        const uint32_t sb = smemBase + (ch & 1) * STG_BYTES;

        #pragma unroll
        for (int ks = 0; ks < 4; ks++) {
            uint32_t Ah[2][4], Al[2][4], Bh[4][4], Bl[4][4];
            #pragma unroll
            for (int im = 0; im < 2; im++) {
                int row = warp_m * 32 + im * 16 + aRowIn;
                uint32_t off = row * 128 + (((ks * 2 + aSel) ^ (row & 7)) << 4);
                ldmat4(Ah[im][0], Ah[im][1], Ah[im][2], Ah[im][3], sb + off);
                ldmat4(Al[im][0], Al[im][1], Al[im][2], Al[im][3], sb + PLANE + off);
            }
            #pragma unroll
            for (int jn = 0; jn < 4; jn++) {
                int nr = warp_n * 64 + jn * 16 + bRowIn;
                uint32_t off = nr * 128 + (((ks * 2 + bSel) ^ (nr & 7)) << 4);
                ldmat4(Bh[jn][0], Bh[jn][1], Bh[jn][2], Bh[jn][3], sb + 2 * PLANE + off);
                ldmat4(Bl[jn][0], Bl[jn][1], Bl[jn][2], Bl[jn][3], sb + 3 * PLANE + off);
            }
            #pragma unroll
            for (int im = 0; im < 2; im++)
                #pragma unroll
                for (int jn = 0; jn < 4; jn++) {
                    // n8 tiles 2*jn (regs 0,1) and 2*jn+1 (regs 2,3)
                    mma_bf16(acc[im][2 * jn],     Ah[im], &Bh[jn][0]);
                    mma_bf16(acc[im][2 * jn],     Ah[im], &Bl[jn][0]);
                    mma_bf16(acc[im][2 * jn],     Al[im], &Bh[jn][0]);
                    mma_bf16(acc[im][2 * jn + 1], Ah[im], &Bh[jn][2]);
                    mma_bf16(acc[im][2 * jn + 1], Ah[im], &Bl[jn][2]);
                    mma_bf16(acc[im][2 * jn + 1], Al[im], &Bh[jn][2]);
                }
        }
        __syncthreads();
        if (ch + 2 < NCHUNK) { loadStage(ch + 2, ch & 1); cp_commit(); }
    }

    // ---- epilogue: scale, stage (swizzled), argmax, coalesced store ----
    float* shOut = (float*)dsm;     // 128x128 fp32 = 64KB (stage 0 reuse)
    const int rb = lane >> 2, cb = (lane & 3) * 2;
    #pragma unroll
    for (int im = 0; im < 2; im++) {
        #pragma unroll
        for (int jn = 0; jn < 8; jn++) {
            #pragma unroll
            for (int k = 0; k < 4; k++) {
                int r = warp_m * 32 + im * 16 + rb + (k >> 1) * 8;
                int c = warp_n * 64 + jn * 8 + cb + (k & 1);
                float v = acc[im][jn][k] * s_pinv[r] * s_tinv[c];
                int scol = (c & ~31) | ((c ^ r) & 31);
                shOut[r * 128 + scol] = v;
            }
        }
    }
    __syncthreads();

    if (doArgmax) {
        int r = tid & 127, half = tid >> 7;
        float bestv = -1e30f;
        int bestn = -1;
        #pragma unroll 16
        for (int j = 0; j < 64; j++) {
            int c = half * 64 + j;
            if (col0 + c < NV) {
                int scol = (c & ~31) | ((c ^ r) & 31);
                float v = shOut[r * 128 + scol];
                if (v > bestv) { bestv = v; bestn = col0 + c; }
            }
        }
        if (bestn >= 0)
            atomicMax(&d_best[row0 + r], packKey(bestv, bestn));
    }

    #pragma unroll
    for (int i = 0; i < 64; i++) {
        int idx = i * 256 + tid;
        int r = idx >> 7, c = idx & 127;
        int gc = col0 + c;
        if (gc < NV) {
            int scol = (c & ~31) | ((c ^ r) & 31);
            __stcs(simOut + (size_t)(row0 + r) * NV + gc, shOut[r * 128 + scol]);
        }
    }
}

// ---------------- K8: decode fused argmax ---------------------------------
__global__ void k_decode(float* __restrict__ nnOut) {
    int t = blockIdx.x * blockDim.x + threadIdx.x;
    if (t < NTOK) nnOut[t] = (float)(~(unsigned)(d_best[t] & 0xFFFFFFFFull));
}

// ---------------- launch ---------------------------------------------------
extern "C" void kernel_launch(void* const* d_in, const int* in_sizes, int n_in,
                              void* d_out, int out_size) {
    const int* utt = (const int*)d_in[0];     // [B,S] int32
    const float* emb = (const float*)d_in[1]; // [V,E] fp32
    const float* grad = (const float*)d_in[2];// [B,S,E] fp32
    float* out = (float*)d_out;

    float* nnOut = nullptr;
    float* simOut = out;
    if (out_size == NTOK * (NV + 1)) {        // tuple order: nn_idx, then sim
        nnOut = out;
        simOut = out + NTOK;
    }

    k_init<<<(NTOK + 255) / 256, 256>>>();
    k_absgrad<<<NTOK, 128>>>(grad);
    k_mask<<<NB, NS>>>();
    k_stats<<<NTOK, 256>>>(grad);
    k_final<<<1, 1>>>();
    k_perturb<<<NTOK, 128>>>(utt, emb, grad);
    k_tnorm<<<NV, 128>>>(emb);
    k_split_emb<<<(NVP * NE / 4 + 255) / 256, 256>>>(emb);

    const int dynSmem = 2 * STG_BYTES;        // 128KB
    static int attrSet = 0;
    if (!attrSet) {
        cudaFuncSetAttribute(k_gemm, cudaFuncAttributeMaxDynamicSharedMemorySize, dynSmem);
        attrSet = 1;
    }
    dim3 g(NBLK, NTOK / TC_M);
    k_gemm<<<g, 256, dynSmem>>>(simOut, nnOut != nullptr);

    if (nnOut) k_decode<<<(NTOK + 255) / 256, 256>>>(nnOut);
}

// round 7
// speedup vs baseline: 3.1216x; 1.2730x over previous
#include <cuda_runtime.h>
#include <cuda_fp16.h>
#include <math.h>
#include <stdint.h>

#define NB 32
#define NS 64
#define NE 512
#define NV 50257
#define NVP 50304             // NV padded to 128
#define NTOK (NB*NS)          // 2048
#define KSEL (NS/2)           // 32
#define EPS_ATK 0.4f
#define STD_MULT 3.0
#define COS_EPS 1e-8f

// GEMM tile config
#define TC_M 128
#define TC_N 128
#define KCH 64                // K per pipeline stage
#define NCHUNK (NE / KCH)     // 8
#define NBLK (NVP / TC_N)     // 393

// ---------------- scratch (device globals; no allocation allowed) ----------
__device__ __half d_pertH[NTOK*NE];      // 2 MB  (single fp16 plane)
__device__ __half d_embH[NVP*NE];        // 51.5 MB
__device__ __half d_embL[NVP*NE];        // 51.5 MB
__device__ float  d_absg[NTOK];
__device__ int    d_mask[NTOK];
__device__ float  d_pinv[NTOK];
__device__ float  d_tinv[NV];
__device__ double d_sum;
__device__ double d_sumsq;
__device__ float  d_lb, d_ub;
__device__ unsigned long long d_best[NTOK];

// ---------------- PTX helpers (baseline ISA only) ---------------------------
__device__ __forceinline__ uint32_t smem_u32(const void* p) {
    uint32_t a;
    asm("{ .reg .u64 t; cvta.to.shared.u64 t, %1; cvt.u32.u64 %0, t; }"
        : "=r"(a) : "l"(p));
    return a;
}
__device__ __forceinline__ void cp_async16(uint32_t dst, const void* src) {
    asm volatile("cp.async.cg.shared.global [%0], [%1], 16;"
                 :: "r"(dst), "l"(src) : "memory");
}
__device__ __forceinline__ void cp_commit() {
    asm volatile("cp.async.commit_group;" ::: "memory");
}
template<int N> __device__ __forceinline__ void cp_wait() {
    asm volatile("cp.async.wait_group %0;" :: "n"(N) : "memory");
}
__device__ __forceinline__ void ldmat4(uint32_t& r0, uint32_t& r1, uint32_t& r2,
                                       uint32_t& r3, uint32_t addr) {
    asm volatile("ldmatrix.sync.aligned.m8n8.x4.shared.b16 {%0,%1,%2,%3}, [%4];"
                 : "=r"(r0), "=r"(r1), "=r"(r2), "=r"(r3) : "r"(addr));
}
__device__ __forceinline__ void mma_f16(float* d, const uint32_t* a, const uint32_t* b) {
    asm volatile(
        "mma.sync.aligned.m16n8k16.row.col.f32.f16.f16.f32 "
        "{%0,%1,%2,%3}, {%4,%5,%6,%7}, {%8,%9}, {%0,%1,%2,%3};"
        : "+f"(d[0]), "+f"(d[1]), "+f"(d[2]), "+f"(d[3])
        : "r"(a[0]), "r"(a[1]), "r"(a[2]), "r"(a[3]), "r"(b[0]), "r"(b[1]));
}

// argmax key: monotone float encoding, ~index for smaller-index-wins on ties
static __device__ __forceinline__ unsigned long long packKey(float v, int n) {
    unsigned u = __float_as_uint(v);
    u = (u & 0x80000000u) ? ~u : (u | 0x80000000u);
    return ((unsigned long long)u << 32) | (unsigned)(~n);
}

// ---------------- reductions ----------------
__device__ __forceinline__ float blockReduceSumF(float v) {
    __shared__ float sh[32];
    int lane = threadIdx.x & 31, w = threadIdx.x >> 5;
    #pragma unroll
    for (int o = 16; o > 0; o >>= 1) v += __shfl_down_sync(0xffffffffu, v, o);
    if (lane == 0) sh[w] = v;
    __syncthreads();
    int nw = (blockDim.x + 31) >> 5;
    v = (threadIdx.x < nw) ? sh[threadIdx.x] : 0.f;
    if (w == 0) {
        #pragma unroll
        for (int o = 16; o > 0; o >>= 1) v += __shfl_down_sync(0xffffffffu, v, o);
    }
    __syncthreads();
    return v;
}

// ---------------- K0: init ------------------------------------------------
__global__ void k_init() {
    int t = blockIdx.x * blockDim.x + threadIdx.x;
    if (t == 0) { d_sum = 0.0; d_sumsq = 0.0; }
    if (t < NTOK) d_best[t] = 0ull;
}

// ---------------- K1: per-token |grad| sum --------------------------------
__global__ void k_absgrad(const float* __restrict__ grad) {
    int t = blockIdx.x;
    const float* p = grad + (size_t)t * NE;
    float s = 0.f;
    for (int e = threadIdx.x; e < NE; e += blockDim.x) s += fabsf(p[e]);
    s = blockReduceSumF(s);
    if (threadIdx.x == 0) d_absg[t] = s;
}

// ---------------- K2: top-k mask (rank count, stable ties) ----------------
__global__ void k_mask() {
    __shared__ float v[NS];
    int b = blockIdx.x, i = threadIdx.x;
    v[i] = d_absg[b * NS + i];
    __syncthreads();
    float me = v[i];
    int rank = 0;
    #pragma unroll 8
    for (int j = 0; j < NS; j++)
        rank += (v[j] > me) || (v[j] == me && j < i);
    d_mask[b * NS + i] = (rank < KSEL) ? 1 : 0;
}

// ---------------- K3: masked sum / sumsq (double accum) -------------------
__global__ void k_stats(const float* __restrict__ grad) {
    int t = blockIdx.x;
    if (!d_mask[t]) return;
    const float* p = grad + (size_t)t * NE;
    double s = 0.0, s2 = 0.0;
    for (int e = threadIdx.x; e < NE; e += blockDim.x) {
        double x = (double)p[e];
        s += x; s2 += x * x;
    }
    __shared__ double sha[32], shb[32];
    int lane = threadIdx.x & 31, w = threadIdx.x >> 5;
    #pragma unroll
    for (int o = 16; o > 0; o >>= 1) {
        s  += __shfl_down_sync(0xffffffffu, s,  o);
        s2 += __shfl_down_sync(0xffffffffu, s2, o);
    }
    if (lane == 0) { sha[w] = s; shb[w] = s2; }
    __syncthreads();
    int nw = (blockDim.x + 31) >> 5;
    if (w == 0) {
        s  = (threadIdx.x < nw) ? sha[threadIdx.x] : 0.0;
        s2 = (threadIdx.x < nw) ? shb[threadIdx.x] : 0.0;
        #pragma unroll
        for (int o = 16; o > 0; o >>= 1) {
            s  += __shfl_down_sync(0xffffffffu, s,  o);
            s2 += __shfl_down_sync(0xffffffffu, s2, o);
        }
        if (lane == 0) { atomicAdd(&d_sum, s); atomicAdd(&d_sumsq, s2); }
    }
}

// ---------------- K4: finalize mean/std -> bounds -------------------------
__global__ void k_final() {
    double n = (double)NB * KSEL * NE;
    double mean = d_sum / n;
    double var = (d_sumsq - n * mean * mean) / (n - 1.0);
    double sd = sqrt(var);
    d_lb = (float)(mean - sd * STD_MULT);
    d_ub = (float)(mean + sd * STD_MULT);
}

// ---------------- K5: perturb + inv norm + fp16 store ---------------------
__global__ void k_perturb(const int* __restrict__ utt,
                          const float* __restrict__ emb,
                          const float* __restrict__ grad) {
    int t = blockIdx.x;
    int u = utt[t];
    int m = d_mask[t];
    float lb = d_lb, ub = d_ub;
    const float* erow = emb + (size_t)u * NE;
    const float* grow = grad + (size_t)t * NE;
    __half* hrow = d_pertH + (size_t)t * NE;
    float acc = 0.f;
    for (int e = threadIdx.x; e < NE; e += blockDim.x) {
        float ev = erow[e];
        float dg = grow[e];
        float p = ev;
        if (m && (dg < lb || dg > ub))
            p += (dg > 0.f) ? EPS_ATK : ((dg < 0.f) ? -EPS_ATK : 0.f);
        hrow[e] = __float2half(p);
        acc += p * p;
    }
    acc = blockReduceSumF(acc);
    if (threadIdx.x == 0)
        d_pinv[t] = 1.f / fmaxf(sqrtf(acc), COS_EPS);
}

// ---------------- K6: fused emb fp16 hi/lo split + row inv norm -----------
// One block (128 threads) per padded vocab row; single pass over emb.
__global__ void k_splitnorm(const float* __restrict__ emb) {
    int row = blockIdx.x;
    int tid = threadIdx.x;                 // 0..127, one float4 each
    float4 v = make_float4(0.f, 0.f, 0.f, 0.f);
    if (row < NV)
        v = __ldg((const float4*)(emb + (size_t)row * NE) + tid);
    __half h0 = __float2half(v.x), h1 = __float2half(v.y);
    __half h2 = __float2half(v.z), h3 = __float2half(v.w);
    __half l0 = __float2half(v.x - __half2float(h0));
    __half l1 = __float2half(v.y - __half2float(h1));
    __half l2 = __float2half(v.z - __half2float(h2));
    __half l3 = __float2half(v.w - __half2float(h3));
    uint2 hv, lv;
    hv.x = (uint32_t)__half_as_ushort(h0) | ((uint32_t)__half_as_ushort(h1) << 16);
    hv.y = (uint32_t)__half_as_ushort(h2) | ((uint32_t)__half_as_ushort(h3) << 16);
    lv.x = (uint32_t)__half_as_ushort(l0) | ((uint32_t)__half_as_ushort(l1) << 16);
    lv.y = (uint32_t)__half_as_ushort(l2) | ((uint32_t)__half_as_ushort(l3) << 16);
    ((uint2*)(d_embH + (size_t)row * NE))[tid] = hv;
    ((uint2*)(d_embL + (size_t)row * NE))[tid] = lv;
    float acc = v.x * v.x + v.y * v.y + v.z * v.z + v.w * v.w;
    acc = blockReduceSumF(acc);
    if (tid == 0 && row < NV)
        d_tinv[row] = 1.f / fmaxf(sqrtf(acc), COS_EPS);
}

// ---------------- K7: HMMA fp16 2-pass GEMM + fused epilogue --------------
// sim = pert @ emb^T  via  Ah*Bh + Ah*Bl  (fp32 accum).
// SMEM per stage: Ah | Bh | Bl, each 128x64 fp16 = 16KB (XOR-swizzled).
#define PLANE 16384
#define STG_BYTES (3*PLANE)   // 48KB

__global__ __launch_bounds__(256, 1) void k_gemm(float* __restrict__ simOut,
                                                 int doArgmax) {
    extern __shared__ char dsm[];
    __shared__ float s_tinv[TC_N];
    __shared__ float s_pinv[TC_M];

    const int tid = threadIdx.x;
    const int wid = tid >> 5;
    const int lane = tid & 31;
    const int warp_m = wid & 3;        // 4 row groups of 32
    const int warp_n = wid >> 2;       // 2 col groups of 64
    const int col0 = blockIdx.x * TC_N;
    const int row0 = blockIdx.y * TC_M;

    if (tid < TC_M) s_pinv[tid] = d_pinv[row0 + tid];
    if (tid < TC_N) {
        int c = col0 + tid;
        s_tinv[tid] = (c < NV) ? d_tinv[c] : 0.f;
    }

    const uint32_t smemBase = smem_u32(dsm);

    // stage loader: 3 planes x 1024 chunks of 16B; 12 chunks/thread
    auto loadStage = [&](int ch, int buf) {
        const int k0 = ch * KCH;
        uint32_t sb = smemBase + buf * STG_BYTES;
        #pragma unroll
        for (int i = 0; i < 4; i++) {
            int q = i * 256 + tid;
            int r = q >> 3, c = q & 7;
            uint32_t dst = sb + r * 128 + ((c ^ (r & 7)) << 4);
            cp_async16(dst,             d_pertH + (size_t)(row0 + r) * NE + k0 + c * 8);
            cp_async16(dst + PLANE,     d_embH  + (size_t)(col0 + r) * NE + k0 + c * 8);
            cp_async16(dst + 2 * PLANE, d_embL  + (size_t)(col0 + r) * NE + k0 + c * 8);
        }
    };

    float acc[2][8][4];
    #pragma unroll
    for (int i = 0; i < 2; i++)
        #pragma unroll
        for (int j = 0; j < 8; j++)
            #pragma unroll
            for (int k = 0; k < 4; k++) acc[i][j][k] = 0.f;

    const int aRowIn = lane & 15;
    const int aSel = lane >> 4;
    const int bRowIn = (lane & 7) + ((lane >> 4) << 3);
    const int bSel = (lane >> 3) & 1;

    loadStage(0, 0); cp_commit();
    loadStage(1, 1); cp_commit();

    for (int ch = 0; ch < NCHUNK; ch++) {
        if (ch < NCHUNK - 1) cp_wait<1>(); else cp_wait<0>();
        __syncthreads();
        const uint32_t sb = smemBase + (ch & 1) * STG_BYTES;

        #pragma unroll
        for (int ks = 0; ks < 4; ks++) {
            uint32_t Ah[2][4], Bh[4][4], Bl[4][4];
            #pragma unroll
            for (int im = 0; im < 2; im++) {
                int row = warp_m * 32 + im * 16 + aRowIn;
                uint32_t off = row * 128 + (((ks * 2 + aSel) ^ (row & 7)) << 4);
                ldmat4(Ah[im][0], Ah[im][1], Ah[im][2], Ah[im][3], sb + off);
            }
            #pragma unroll
            for (int jn = 0; jn < 4; jn++) {
                int nr = warp_n * 64 + jn * 16 + bRowIn;
                uint32_t off = nr * 128 + (((ks * 2 + bSel) ^ (nr & 7)) << 4);
                ldmat4(Bh[jn][0], Bh[jn][1], Bh[jn][2], Bh[jn][3], sb + PLANE + off);
                ldmat4(Bl[jn][0], Bl[jn][1], Bl[jn][2], Bl[jn][3], sb + 2 * PLANE + off);
            }
            #pragma unroll
            for (int im = 0; im < 2; im++)
                #pragma unroll
                for (int jn = 0; jn < 4; jn++) {
                    mma_f16(acc[im][2 * jn],     Ah[im], &Bh[jn][0]);
                    mma_f16(acc[im][2 * jn],     Ah[im], &Bl[jn][0]);
                    mma_f16(acc[im][2 * jn + 1], Ah[im], &Bh[jn][2]);
                    mma_f16(acc[im][2 * jn + 1], Ah[im], &Bl[jn][2]);
                }
        }
        __syncthreads();
        if (ch + 2 < NCHUNK) { loadStage(ch + 2, ch & 1); cp_commit(); }
    }

    // ---- epilogue: scale, stage (swizzled), argmax, coalesced store ----
    float* shOut = (float*)dsm;     // 128x128 fp32 = 64KB (fits in 96KB)
    const int rb = lane >> 2, cb = (lane & 3) * 2;
    #pragma unroll
    for (int im = 0; im < 2; im++) {
        #pragma unroll
        for (int jn = 0; jn < 8; jn++) {
            #pragma unroll
            for (int k = 0; k < 4; k++) {
                int r = warp_m * 32 + im * 16 + rb + (k >> 1) * 8;
                int c = warp_n * 64 + jn * 8 + cb + (k & 1);
                float v = acc[im][jn][k] * s_pinv[r] * s_tinv[c];
                int scol = (c & ~31) | ((c ^ r) & 31);
                shOut[r * 128 + scol] = v;
            }
        }
    }
    __syncthreads();

    if (doArgmax) {
        int r = tid & 127, half = tid >> 7;
        float bestv = -1e30f;
        int bestn = -1;
        #pragma unroll 16
        for (int j = 0; j < 64; j++) {
            int c = half * 64 + j;
            if (col0 + c < NV) {
                int scol = (c & ~31) | ((c ^ r) & 31);
                float v = shOut[r * 128 + scol];
                if (v > bestv) { bestv = v; bestn = col0 + c; }
            }
        }
        if (bestn >= 0)
            atomicMax(&d_best[row0 + r], packKey(bestv, bestn));
    }

    #pragma unroll
    for (int i = 0; i < 64; i++) {
        int idx = i * 256 + tid;
        int r = idx >> 7, c = idx & 127;
        int gc = col0 + c;
        if (gc < NV) {
            int scol = (c & ~31) | ((c ^ r) & 31);
            __stcs(simOut + (size_t)(row0 + r) * NV + gc, shOut[r * 128 + scol]);
        }
    }
}

// ---------------- K8: decode fused argmax ---------------------------------
__global__ void k_decode(float* __restrict__ nnOut) {
    int t = blockIdx.x * blockDim.x + threadIdx.x;
    if (t < NTOK) nnOut[t] = (float)(~(unsigned)(d_best[t] & 0xFFFFFFFFull));
}

// ---------------- launch ---------------------------------------------------
extern "C" void kernel_launch(void* const* d_in, const int* in_sizes, int n_in,
                              void* d_out, int out_size) {
    const int* utt = (const int*)d_in[0];     // [B,S] int32
    const float* emb = (const float*)d_in[1]; // [V,E] fp32
    const float* grad = (const float*)d_in[2];// [B,S,E] fp32
    float* out = (float*)d_out;

    float* nnOut = nullptr;
    float* simOut = out;
    if (out_size == NTOK * (NV + 1)) {        // tuple order: nn_idx, then sim
        nnOut = out;
        simOut = out + NTOK;
    }

    k_init<<<(NTOK + 255) / 256, 256>>>();
    k_absgrad<<<NTOK, 128>>>(grad);
    k_mask<<<NB, NS>>>();
    k_stats<<<NTOK, 256>>>(grad);
    k_final<<<1, 1>>>();
    k_perturb<<<NTOK, 128>>>(utt, emb, grad);
    k_splitnorm<<<NVP, 128>>>(emb);

    const int dynSmem = 2 * STG_BYTES;        // 96KB
    static int attrSet = 0;
    if (!attrSet) {
        cudaFuncSetAttribute(k_gemm, cudaFuncAttributeMaxDynamicSharedMemorySize, dynSmem);
        attrSet = 1;
    }
    dim3 g(NBLK, NTOK / TC_M);
    k_gemm<<<g, 256, dynSmem>>>(simOut, nnOut != nullptr);

    if (nnOut) k_decode<<<(NTOK + 255) / 256, 256>>>(nnOut);
}

// round 8
// speedup vs baseline: 5.8344x; 1.8690x over previous
#include <cuda_runtime.h>
#include <cuda_fp16.h>
#include <math.h>
#include <stdint.h>

#define NB 32
#define NS 64
#define NE 512
#define NV 50257
#define NVP 50304             // NV padded to 128
#define NTOK (NB*NS)          // 2048
#define KSEL (NS/2)           // 32
#define EPS_ATK 0.4f
#define STD_MULT 3.0
#define COS_EPS 1e-8f

// GEMM tile config
#define TC_M 128
#define TC_N 128
#define KCH 64                // K per pipeline stage
#define NCHUNK (NE / KCH)     // 8
#define NBLK (NVP / TC_N)     // 393

// ---------------- scratch (device globals; no allocation allowed) ----------
__device__ __half d_pertH[NTOK*NE];      // 2 MB
__device__ __half d_embH[NVP*NE];        // 51.5 MB
__device__ float  d_absg[NTOK];
__device__ int    d_mask[NTOK];
__device__ float  d_pinv[NTOK];
__device__ float  d_tinv[NV];
__device__ double d_sum;
__device__ double d_sumsq;
__device__ float  d_lb, d_ub;
__device__ unsigned long long d_best[NTOK];

// ---------------- PTX helpers (baseline ISA only) ---------------------------
__device__ __forceinline__ uint32_t smem_u32(const void* p) {
    uint32_t a;
    asm("{ .reg .u64 t; cvta.to.shared.u64 t, %1; cvt.u32.u64 %0, t; }"
        : "=r"(a) : "l"(p));
    return a;
}
__device__ __forceinline__ void cp_async16(uint32_t dst, const void* src) {
    asm volatile("cp.async.cg.shared.global [%0], [%1], 16;"
                 :: "r"(dst), "l"(src) : "memory");
}
__device__ __forceinline__ void cp_commit() {
    asm volatile("cp.async.commit_group;" ::: "memory");
}
template<int N> __device__ __forceinline__ void cp_wait() {
    asm volatile("cp.async.wait_group %0;" :: "n"(N) : "memory");
}
__device__ __forceinline__ void ldmat4(uint32_t& r0, uint32_t& r1, uint32_t& r2,
                                       uint32_t& r3, uint32_t addr) {
    asm volatile("ldmatrix.sync.aligned.m8n8.x4.shared.b16 {%0,%1,%2,%3}, [%4];"
                 : "=r"(r0), "=r"(r1), "=r"(r2), "=r"(r3) : "r"(addr));
}
__device__ __forceinline__ void mma_f16(float* d, const uint32_t* a, const uint32_t* b) {
    asm volatile(
        "mma.sync.aligned.m16n8k16.row.col.f32.f16.f16.f32 "
        "{%0,%1,%2,%3}, {%4,%5,%6,%7}, {%8,%9}, {%0,%1,%2,%3};"
        : "+f"(d[0]), "+f"(d[1]), "+f"(d[2]), "+f"(d[3])
        : "r"(a[0]), "r"(a[1]), "r"(a[2]), "r"(a[3]), "r"(b[0]), "r"(b[1]));
}

// argmax key: monotone float encoding, ~index for smaller-index-wins on ties
static __device__ __forceinline__ unsigned long long packKey(float v, int n) {
    unsigned u = __float_as_uint(v);
    u = (u & 0x80000000u) ? ~u : (u | 0x80000000u);
    return ((unsigned long long)u << 32) | (unsigned)(~n);
}

// ---------------- reductions ----------------
__device__ __forceinline__ float blockReduceSumF(float v) {
    __shared__ float sh[32];
    int lane = threadIdx.x & 31, w = threadIdx.x >> 5;
    #pragma unroll
    for (int o = 16; o > 0; o >>= 1) v += __shfl_down_sync(0xffffffffu, v, o);
    if (lane == 0) sh[w] = v;
    __syncthreads();
    int nw = (blockDim.x + 31) >> 5;
    v = (threadIdx.x < nw) ? sh[threadIdx.x] : 0.f;
    if (w == 0) {
        #pragma unroll
        for (int o = 16; o > 0; o >>= 1) v += __shfl_down_sync(0xffffffffu, v, o);
    }
    __syncthreads();
    return v;
}

// ---------------- K0: init ------------------------------------------------
__global__ void k_init() {
    int t = blockIdx.x * blockDim.x + threadIdx.x;
    if (t == 0) { d_sum = 0.0; d_sumsq = 0.0; }
    if (t < NTOK) d_best[t] = 0ull;
}

// ---------------- K1: per-token |grad| sum --------------------------------
__global__ void k_absgrad(const float* __restrict__ grad) {
    int t = blockIdx.x;
    const float* p = grad + (size_t)t * NE;
    float s = 0.f;
    for (int e = threadIdx.x; e < NE; e += blockDim.x) s += fabsf(p[e]);
    s = blockReduceSumF(s);
    if (threadIdx.x == 0) d_absg[t] = s;
}

// ---------------- K2: top-k mask (rank count, stable ties) ----------------
__global__ void k_mask() {
    __shared__ float v[NS];
    int b = blockIdx.x, i = threadIdx.x;
    v[i] = d_absg[b * NS + i];
    __syncthreads();
    float me = v[i];
    int rank = 0;
    #pragma unroll 8
    for (int j = 0; j < NS; j++)
        rank += (v[j] > me) || (v[j] == me && j < i);
    d_mask[b * NS + i] = (rank < KSEL) ? 1 : 0;
}

// ---------------- K3: masked sum / sumsq (double accum) -------------------
__global__ void k_stats(const float* __restrict__ grad) {
    int t = blockIdx.x;
    if (!d_mask[t]) return;
    const float* p = grad + (size_t)t * NE;
    double s = 0.0, s2 = 0.0;
    for (int e = threadIdx.x; e < NE; e += blockDim.x) {
        double x = (double)p[e];
        s += x; s2 += x * x;
    }
    __shared__ double sha[32], shb[32];
    int lane = threadIdx.x & 31, w = threadIdx.x >> 5;
    #pragma unroll
    for (int o = 16; o > 0; o >>= 1) {
        s  += __shfl_down_sync(0xffffffffu, s,  o);
        s2 += __shfl_down_sync(0xffffffffu, s2, o);
    }
    if (lane == 0) { sha[w] = s; shb[w] = s2; }
    __syncthreads();
    int nw = (blockDim.x + 31) >> 5;
    if (w == 0) {
        s  = (threadIdx.x < nw) ? sha[threadIdx.x] : 0.0;
        s2 = (threadIdx.x < nw) ? shb[threadIdx.x] : 0.0;
        #pragma unroll
        for (int o = 16; o > 0; o >>= 1) {
            s  += __shfl_down_sync(0xffffffffu, s,  o);
            s2 += __shfl_down_sync(0xffffffffu, s2, o);
        }
        if (lane == 0) { atomicAdd(&d_sum, s); atomicAdd(&d_sumsq, s2); }
    }
}

// ---------------- K4: finalize mean/std -> bounds -------------------------
__global__ void k_final() {
    double n = (double)NB * KSEL * NE;
    double mean = d_sum / n;
    double var = (d_sumsq - n * mean * mean) / (n - 1.0);
    double sd = sqrt(var);
    d_lb = (float)(mean - sd * STD_MULT);
    d_ub = (float)(mean + sd * STD_MULT);
}

// ---------------- K5: perturb + inv norm + fp16 store ---------------------
__global__ void k_perturb(const int* __restrict__ utt,
                          const float* __restrict__ emb,
                          const float* __restrict__ grad) {
    int t = blockIdx.x;
    int u = utt[t];
    int m = d_mask[t];
    float lb = d_lb, ub = d_ub;
    const float* erow = emb + (size_t)u * NE;
    const float* grow = grad + (size_t)t * NE;
    __half* hrow = d_pertH + (size_t)t * NE;
    float acc = 0.f;
    for (int e = threadIdx.x; e < NE; e += blockDim.x) {
        float ev = erow[e];
        float dg = grow[e];
        float p = ev;
        if (m && (dg < lb || dg > ub))
            p += (dg > 0.f) ? EPS_ATK : ((dg < 0.f) ? -EPS_ATK : 0.f);
        hrow[e] = __float2half(p);
        acc += p * p;
    }
    acc = blockReduceSumF(acc);
    if (threadIdx.x == 0)
        d_pinv[t] = 1.f / fmaxf(sqrtf(acc), COS_EPS);
}

// ---------------- K6: fused emb fp16 convert + row inv norm ---------------
__global__ void k_splitnorm(const float* __restrict__ emb) {
    int row = blockIdx.x;
    int tid = threadIdx.x;                 // 0..127, one float4 each
    float4 v = make_float4(0.f, 0.f, 0.f, 0.f);
    if (row < NV)
        v = __ldg((const float4*)(emb + (size_t)row * NE) + tid);
    __half h0 = __float2half(v.x), h1 = __float2half(v.y);
    __half h2 = __float2half(v.z), h3 = __float2half(v.w);
    uint2 hv;
    hv.x = (uint32_t)__half_as_ushort(h0) | ((uint32_t)__half_as_ushort(h1) << 16);
    hv.y = (uint32_t)__half_as_ushort(h2) | ((uint32_t)__half_as_ushort(h3) << 16);
    ((uint2*)(d_embH + (size_t)row * NE))[tid] = hv;
    float acc = v.x * v.x + v.y * v.y + v.z * v.z + v.w * v.w;
    acc = blockReduceSumF(acc);
    if (tid == 0 && row < NV)
        d_tinv[row] = 1.f / fmaxf(sqrtf(acc), COS_EPS);
}

// ---------------- K7: HMMA fp16 single-pass GEMM + fused epilogue ---------
// sim = pert @ emb^T (fp32 accum). SMEM/stage: A | B, each 128x64 fp16 = 16KB.
#define PLANE 16384
#define STG_BYTES (2*PLANE)   // 32KB

__global__ __launch_bounds__(256, 2) void k_gemm(float* __restrict__ simOut,
                                                 int doArgmax) {
    extern __shared__ char dsm[];
    __shared__ float s_tinv[TC_N];
    __shared__ float s_pinv[TC_M];

    const int tid = threadIdx.x;
    const int wid = tid >> 5;
    const int lane = tid & 31;
    const int warp_m = wid & 3;        // 4 row groups of 32
    const int warp_n = wid >> 2;       // 2 col groups of 64
    const int col0 = blockIdx.x * TC_N;
    const int row0 = blockIdx.y * TC_M;

    if (tid < TC_M) s_pinv[tid] = d_pinv[row0 + tid];
    if (tid < TC_N) {
        int c = col0 + tid;
        s_tinv[tid] = (c < NV) ? d_tinv[c] : 0.f;
    }

    const uint32_t smemBase = smem_u32(dsm);

    // stage loader: 2 planes x 1024 chunks of 16B; 8 chunks/thread
    auto loadStage = [&](int ch, int buf) {
        const int k0 = ch * KCH;
        uint32_t sb = smemBase + buf * STG_BYTES;
        #pragma unroll
        for (int i = 0; i < 4; i++) {
            int q = i * 256 + tid;
            int r = q >> 3, c = q & 7;
            uint32_t dst = sb + r * 128 + ((c ^ (r & 7)) << 4);
            cp_async16(dst,         d_pertH + (size_t)(row0 + r) * NE + k0 + c * 8);
            cp_async16(dst + PLANE, d_embH  + (size_t)(col0 + r) * NE + k0 + c * 8);
        }
    };

    float acc[2][8][4];
    #pragma unroll
    for (int i = 0; i < 2; i++)
        #pragma unroll
        for (int j = 0; j < 8; j++)
            #pragma unroll
            for (int k = 0; k < 4; k++) acc[i][j][k] = 0.f;

    const int aRowIn = lane & 15;
    const int aSel = lane >> 4;
    const int bRowIn = (lane & 7) + ((lane >> 4) << 3);
    const int bSel = (lane >> 3) & 1;

    loadStage(0, 0); cp_commit();
    loadStage(1, 1); cp_commit();

    for (int ch = 0; ch < NCHUNK; ch++) {
        if (ch < NCHUNK - 1) cp_wait<1>(); else cp_wait<0>();
        __syncthreads();
        const uint32_t sb = smemBase + (ch & 1) * STG_BYTES;

        #pragma unroll
        for (int ks = 0; ks < 4; ks++) {
            uint32_t Ah[2][4], Bh[4][4];
            #pragma unroll
            for (int im = 0; im < 2; im++) {
                int row = warp_m * 32 + im * 16 + aRowIn;
                uint32_t off = row * 128 + (((ks * 2 + aSel) ^ (row & 7)) << 4);
                ldmat4(Ah[im][0], Ah[im][1], Ah[im][2], Ah[im][3], sb + off);
            }
            #pragma unroll
            for (int jn = 0; jn < 4; jn++) {
                int nr = warp_n * 64 + jn * 16 + bRowIn;
                uint32_t off = nr * 128 + (((ks * 2 + bSel) ^ (nr & 7)) << 4);
                ldmat4(Bh[jn][0], Bh[jn][1], Bh[jn][2], Bh[jn][3], sb + PLANE + off);
            }
            #pragma unroll
            for (int im = 0; im < 2; im++)
                #pragma unroll
                for (int jn = 0; jn < 4; jn++) {
                    mma_f16(acc[im][2 * jn],     Ah[im], &Bh[jn][0]);
                    mma_f16(acc[im][2 * jn + 1], Ah[im], &Bh[jn][2]);
                }
        }
        __syncthreads();
        if (ch + 2 < NCHUNK) { loadStage(ch + 2, ch & 1); cp_commit(); }
    }

    // ---- epilogue: scale, stage (swizzled), argmax, coalesced store ----
    float* shOut = (float*)dsm;     // 128x128 fp32 = 64KB (both stage buffers)
    const int rb = lane >> 2, cb = (lane & 3) * 2;
    #pragma unroll
    for (int im = 0; im < 2; im++) {
        #pragma unroll
        for (int jn = 0; jn < 8; jn++) {
            #pragma unroll
            for (int k = 0; k < 4; k++) {
                int r = warp_m * 32 + im * 16 + rb + (k >> 1) * 8;
                int c = warp_n * 64 + jn * 8 + cb + (k & 1);
                float v = acc[im][jn][k] * s_pinv[r] * s_tinv[c];
                int scol = (c & ~31) | ((c ^ r) & 31);
                shOut[r * 128 + scol] = v;
            }
        }
    }
    __syncthreads();

    if (doArgmax) {
        int r = tid & 127, half = tid >> 7;
        float bestv = -1e30f;
        int bestn = -1;
        #pragma unroll 16
        for (int j = 0; j < 64; j++) {
            int c = half * 64 + j;
            if (col0 + c < NV) {
                int scol = (c & ~31) | ((c ^ r) & 31);
                float v = shOut[r * 128 + scol];
                if (v > bestv) { bestv = v; bestn = col0 + c; }
            }
        }
        if (bestn >= 0)
            atomicMax(&d_best[row0 + r], packKey(bestv, bestn));
    }

    #pragma unroll
    for (int i = 0; i < 64; i++) {
        int idx = i * 256 + tid;
        int r = idx >> 7, c = idx & 127;
        int gc = col0 + c;
        if (gc < NV) {
            int scol = (c & ~31) | ((c ^ r) & 31);
            __stcs(simOut + (size_t)(row0 + r) * NV + gc, shOut[r * 128 + scol]);
        }
    }
}

// ---------------- K8: decode fused argmax ---------------------------------
__global__ void k_decode(float* __restrict__ nnOut) {
    int t = blockIdx.x * blockDim.x + threadIdx.x;
    if (t < NTOK) nnOut[t] = (float)(~(unsigned)(d_best[t] & 0xFFFFFFFFull));
}

// ---------------- launch ---------------------------------------------------
extern "C" void kernel_launch(void* const* d_in, const int* in_sizes, int n_in,
                              void* d_out, int out_size) {
    const int* utt = (const int*)d_in[0];     // [B,S] int32
    const float* emb = (const float*)d_in[1]; // [V,E] fp32
    const float* grad = (const float*)d_in[2];// [B,S,E] fp32
    float* out = (float*)d_out;

    float* nnOut = nullptr;
    float* simOut = out;
    if (out_size == NTOK * (NV + 1)) {        // tuple order: nn_idx, then sim
        nnOut = out;
        simOut = out + NTOK;
    }

    k_init<<<(NTOK + 255) / 256, 256>>>();
    k_absgrad<<<NTOK, 128>>>(grad);
    k_mask<<<NB, NS>>>();
    k_stats<<<NTOK, 256>>>(grad);
    k_final<<<1, 1>>>();
    k_perturb<<<NTOK, 128>>>(utt, emb, grad);
    k_splitnorm<<<NVP, 128>>>(emb);

    const int dynSmem = 2 * STG_BYTES;        // 64KB
    static int attrSet = 0;
    if (!attrSet) {
        cudaFuncSetAttribute(k_gemm, cudaFuncAttributeMaxDynamicSharedMemorySize, dynSmem);
        attrSet = 1;
    }
    dim3 g(NBLK, NTOK / TC_M);
    k_gemm<<<g, 256, dynSmem>>>(simOut, nnOut != nullptr);

    if (nnOut) k_decode<<<(NTOK + 255) / 256, 256>>>(nnOut);
}

// round 10
// speedup vs baseline: 6.6140x; 1.1336x over previous
#include <cuda_runtime.h>
#include <cuda_fp16.h>
#include <math.h>
#include <stdint.h>

#define NB 32
#define NS 64
#define NE 512
#define NV 50257
#define NVP 50304             // NV padded to 128
#define NTOK (NB*NS)          // 2048
#define KSEL (NS/2)           // 32
#define EPS_ATK 0.4f
#define STD_MULT 3.0
#define COS_EPS 1e-8f

// GEMM tile config
#define TC_M 128
#define TC_N 128
#define KCH 64
#define NCHUNK (NE / KCH)     // 8
#define NBLK (NVP / TC_N)     // 393

// ---------------- scratch (device globals; no allocation allowed) ----------
__device__ __half d_pertH[NTOK*NE];      // 2 MB
__device__ __half d_embH[NVP*NE];        // 51.5 MB
__device__ int    d_mask[NTOK];
__device__ float  d_pinv[NTOK];
__device__ float  d_tinv[NV];
__device__ double d_bsum[NB];
__device__ double d_bsumsq[NB];
__device__ unsigned long long d_best[NTOK];

// ---------------- PTX helpers (baseline ISA only) ---------------------------
__device__ __forceinline__ uint32_t smem_u32(const void* p) {
    uint32_t a;
    asm("{ .reg .u64 t; cvta.to.shared.u64 t, %1; cvt.u32.u64 %0, t; }"
        : "=r"(a) : "l"(p));
    return a;
}
__device__ __forceinline__ void cp_async16(uint32_t dst, const void* src) {
    asm volatile("cp.async.cg.shared.global [%0], [%1], 16;"
                 :: "r"(dst), "l"(src) : "memory");
}
__device__ __forceinline__ void cp_commit() {
    asm volatile("cp.async.commit_group;" ::: "memory");
}
template<int N> __device__ __forceinline__ void cp_wait() {
    asm volatile("cp.async.wait_group %0;" :: "n"(N) : "memory");
}
__device__ __forceinline__ void ldmat4(uint32_t& r0, uint32_t& r1, uint32_t& r2,
                                       uint32_t& r3, uint32_t addr) {
    asm volatile("ldmatrix.sync.aligned.m8n8.x4.shared.b16 {%0,%1,%2,%3}, [%4];"
                 : "=r"(r0), "=r"(r1), "=r"(r2), "=r"(r3) : "r"(addr));
}
__device__ __forceinline__ void mma_f16(float* d, const uint32_t* a, const uint32_t* b) {
    asm volatile(
        "mma.sync.aligned.m16n8k16.row.col.f32.f16.f16.f32 "
        "{%0,%1,%2,%3}, {%4,%5,%6,%7}, {%8,%9}, {%0,%1,%2,%3};"
        : "+f"(d[0]), "+f"(d[1]), "+f"(d[2]), "+f"(d[3])
        : "r"(a[0]), "r"(a[1]), "r"(a[2]), "r"(a[3]), "r"(b[0]), "r"(b[1]));
}

// argmax key: monotone float encoding, ~index for smaller-index-wins on ties
static __device__ __forceinline__ unsigned long long packKey(float v, int n) {
    unsigned u = __float_as_uint(v);
    u = (u & 0x80000000u) ? ~u : (u | 0x80000000u);
    return ((unsigned long long)u << 32) | (unsigned)(~n);
}

// ---------------- K1: fused prep ------------------------------------------
// Blocks [0, NVP): emb fp16 convert + vocab row inv-norm (128 thr, 1 f4 each)
// Blocks [NVP, NVP+NB): per-batch |grad| sums -> top-k mask -> masked stats
__global__ void k_prep(const float* __restrict__ emb,
                       const float* __restrict__ grad) {
    const int tid = threadIdx.x, lane = tid & 31, w = tid >> 5;
    if (blockIdx.x < NVP) {
        int row = blockIdx.x;
        float4 v = make_float4(0.f, 0.f, 0.f, 0.f);
        if (row < NV)
            v = __ldg((const float4*)(emb + (size_t)row * NE) + tid);
        __half h0 = __float2half(v.x), h1 = __float2half(v.y);
        __half h2 = __float2half(v.z), h3 = __float2half(v.w);
        uint2 hv;
        hv.x = (uint32_t)__half_as_ushort(h0) | ((uint32_t)__half_as_ushort(h1) << 16);
        hv.y = (uint32_t)__half_as_ushort(h2) | ((uint32_t)__half_as_ushort(h3) << 16);
        ((uint2*)(d_embH + (size_t)row * NE))[tid] = hv;
        float acc = v.x * v.x + v.y * v.y + v.z * v.z + v.w * v.w;
        __shared__ float sh[4];
        #pragma unroll
        for (int o = 16; o > 0; o >>= 1) acc += __shfl_down_sync(0xffffffffu, acc, o);
        if (lane == 0) sh[w] = acc;
        __syncthreads();
        if (tid == 0 && row < NV) {
            float s = sh[0] + sh[1] + sh[2] + sh[3];
            d_tinv[row] = 1.f / fmaxf(sqrtf(s), COS_EPS);
        }
    } else {
        int b = blockIdx.x - NVP;
        __shared__ float s_absg[NS];
        __shared__ int s_msk[NS];
        __shared__ double s_d[8];
        // pass 1: warp w handles tokens w, w+4, ... (16 tokens each)
        for (int tok = w; tok < NS; tok += 4) {
            const float4* p = (const float4*)(grad + (size_t)(b * NS + tok) * NE);
            float s = 0.f;
            #pragma unroll 4
            for (int i = lane; i < NE / 4; i += 32) {
                float4 v = p[i];
                s += fabsf(v.x) + fabsf(v.y) + fabsf(v.z) + fabsf(v.w);
            }
            #pragma unroll
            for (int o = 16; o > 0; o >>= 1) s += __shfl_down_sync(0xffffffffu, s, o);
            if (lane == 0) s_absg[tok] = s;
        }
        __syncthreads();
        // top-k mask by rank count (stable ties)
        if (tid < NS) {
            float me = s_absg[tid];
            int rank = 0;
            #pragma unroll 8
            for (int j = 0; j < NS; j++)
                rank += (s_absg[j] > me) || (s_absg[j] == me && j < tid);
            int mk = (rank < KSEL) ? 1 : 0;
            s_msk[tid] = mk;
            d_mask[b * NS + tid] = mk;
        }
        __syncthreads();
        // pass 2: masked sum / sumsq (L2-hot re-read, double accum)
        double s = 0.0, s2 = 0.0;
        for (int tok = w; tok < NS; tok += 4) {
            if (!s_msk[tok]) continue;
            const float4* p = (const float4*)(grad + (size_t)(b * NS + tok) * NE);
            #pragma unroll 4
            for (int i = lane; i < NE / 4; i += 32) {
                float4 v = p[i];
                double x;
                x = v.x; s += x; s2 += x * x;
                x = v.y; s += x; s2 += x * x;
                x = v.z; s += x; s2 += x * x;
                x = v.w; s += x; s2 += x * x;
            }
        }
        #pragma unroll
        for (int o = 16; o > 0; o >>= 1) {
            s  += __shfl_down_sync(0xffffffffu, s,  o);
            s2 += __shfl_down_sync(0xffffffffu, s2, o);
        }
        if (lane == 0) { s_d[w] = s; s_d[4 + w] = s2; }
        __syncthreads();
        if (tid == 0) {
            d_bsum[b]   = s_d[0] + s_d[1] + s_d[2] + s_d[3];
            d_bsumsq[b] = s_d[4] + s_d[5] + s_d[6] + s_d[7];
        }
    }
}

// ---------------- K2: perturb + inv norm + fp16 store + bounds ------------
__global__ void k_perturb(const int* __restrict__ utt,
                          const float* __restrict__ emb,
                          const float* __restrict__ grad) {
    __shared__ float s_bounds[2];
    __shared__ float sh[4];
    const int tid = threadIdx.x, lane = tid & 31, w = tid >> 5;
    const int t = blockIdx.x;
    // redundant per-block bounds computation from 32 batch partials
    if (w == 0) {
        double s = d_bsum[lane], s2 = d_bsumsq[lane];
        #pragma unroll
        for (int o = 16; o > 0; o >>= 1) {
            s  += __shfl_down_sync(0xffffffffu, s,  o);
            s2 += __shfl_down_sync(0xffffffffu, s2, o);
        }
        if (lane == 0) {
            double n = (double)NB * KSEL * NE;
            double mean = s / n;
            double var = (s2 - n * mean * mean) / (n - 1.0);
            double sd = sqrt(var);
            s_bounds[0] = (float)(mean - sd * STD_MULT);
            s_bounds[1] = (float)(mean + sd * STD_MULT);
            d_best[t] = 0ull;
        }
    }
    __syncthreads();
    const float lb = s_bounds[0], ub = s_bounds[1];
    const int u = utt[t];
    const int m = d_mask[t];
    const float* erow = emb + (size_t)u * NE;
    const float* grow = grad + (size_t)t * NE;
    __half* hrow = d_pertH + (size_t)t * NE;
    float acc = 0.f;
    for (int e = tid; e < NE; e += blockDim.x) {
        float ev = erow[e];
        float dg = grow[e];
        float p = ev;
        if (m && (dg < lb || dg > ub))
            p += (dg > 0.f) ? EPS_ATK : ((dg < 0.f) ? -EPS_ATK : 0.f);
        hrow[e] = __float2half(p);
        acc += p * p;
    }
    #pragma unroll
    for (int o = 16; o > 0; o >>= 1) acc += __shfl_down_sync(0xffffffffu, acc, o);
    if (lane == 0) sh[w] = acc;
    __syncthreads();
    if (tid == 0) {
        float s = sh[0] + sh[1] + sh[2] + sh[3];
        d_pinv[t] = 1.f / fmaxf(sqrtf(s), COS_EPS);
    }
}

// ---------------- K3: HMMA fp16 GEMM + register-direct fused epilogue -----
#define PLANE 16384
#define STG_BYTES (2*PLANE)   // 32KB

__global__ __launch_bounds__(256, 2) void k_gemm(float* __restrict__ simOut,
                                                 int doArgmax) {
    extern __shared__ char dsm[];
    __shared__ float s_tinv[TC_N];
    __shared__ float s_pinv[TC_M];

    const int tid = threadIdx.x;
    const int wid = tid >> 5;
    const int lane = tid & 31;
    const int warp_m = wid & 3;        // 4 row groups of 32
    const int warp_n = wid >> 2;       // 2 col groups of 64
    const int col0 = blockIdx.x * TC_N;
    const int row0 = blockIdx.y * TC_M;

    if (tid < TC_M) s_pinv[tid] = d_pinv[row0 + tid];
    if (tid < TC_N) {
        int c = col0 + tid;
        s_tinv[tid] = (c < NV) ? d_tinv[c] : 0.f;
    }

    const uint32_t smemBase = smem_u32(dsm);

    auto loadStage = [&](int ch, int buf) {
        const int k0 = ch * KCH;
        uint32_t sb = smemBase + buf * STG_BYTES;
        #pragma unroll
        for (int i = 0; i < 4; i++) {
            int q = i * 256 + tid;
            int r = q >> 3, c = q & 7;
            uint32_t dst = sb + r * 128 + ((c ^ (r & 7)) << 4);
            cp_async16(dst,         d_pertH + (size_t)(row0 + r) * NE + k0 + c * 8);
            cp_async16(dst + PLANE, d_embH  + (size_t)(col0 + r) * NE + k0 + c * 8);
        }
    };

    float acc[2][8][4];
    #pragma unroll
    for (int i = 0; i < 2; i++)
        #pragma unroll
        for (int j = 0; j < 8; j++)
            #pragma unroll
            for (int k = 0; k < 4; k++) acc[i][j][k] = 0.f;

    const int aRowIn = lane & 15;
    const int aSel = lane >> 4;
    const int bRowIn = (lane & 7) + ((lane >> 4) << 3);
    const int bSel = (lane >> 3) & 1;

    loadStage(0, 0); cp_commit();
    loadStage(1, 1); cp_commit();

    for (int ch = 0; ch < NCHUNK; ch++) {
        if (ch < NCHUNK - 1) cp_wait<1>(); else cp_wait<0>();
        __syncthreads();
        const uint32_t sb = smemBase + (ch & 1) * STG_BYTES;

        #pragma unroll
        for (int ks = 0; ks < 4; ks++) {
            uint32_t Ah[2][4], Bh[4][4];
            #pragma unroll
            for (int im = 0; im < 2; im++) {
                int row = warp_m * 32 + im * 16 + aRowIn;
                uint32_t off = row * 128 + (((ks * 2 + aSel) ^ (row & 7)) << 4);
                ldmat4(Ah[im][0], Ah[im][1], Ah[im][2], Ah[im][3], sb + off);
            }
            #pragma unroll
            for (int jn = 0; jn < 4; jn++) {
                int nr = warp_n * 64 + jn * 16 + bRowIn;
                uint32_t off = nr * 128 + (((ks * 2 + bSel) ^ (nr & 7)) << 4);
                ldmat4(Bh[jn][0], Bh[jn][1], Bh[jn][2], Bh[jn][3], sb + PLANE + off);
            }
            #pragma unroll
            for (int im = 0; im < 2; im++)
                #pragma unroll
                for (int jn = 0; jn < 4; jn++) {
                    mma_f16(acc[im][2 * jn],     Ah[im], &Bh[jn][0]);
                    mma_f16(acc[im][2 * jn + 1], Ah[im], &Bh[jn][2]);
                }
        }
        __syncthreads();
        if (ch + 2 < NCHUNK) { loadStage(ch + 2, ch & 1); cp_commit(); }
    }

    // ---- register-direct epilogue: scale, scalar streaming stores, argmax
    // (scalar STG.32 only: row base simOut + r*NV has 4B alignment since NV
    //  is odd — a float2 store here traps with misaligned address)
    const int rb = lane >> 2, cb = (lane & 3) * 2;
    #pragma unroll
    for (int im = 0; im < 2; im++) {
        #pragma unroll
        for (int kh = 0; kh < 2; kh++) {
            const int r = warp_m * 32 + im * 16 + rb + kh * 8;
            const float pi = s_pinv[r];
            float* orow = simOut + (size_t)(row0 + r) * NV;
            float bv = -1e30f;
            int bn = -1;
            #pragma unroll
            for (int jn = 0; jn < 8; jn++) {
                const int c = warp_n * 64 + jn * 8 + cb;
                const int gc = col0 + c;
                float v0 = acc[im][jn][kh * 2]     * pi * s_tinv[c];
                float v1 = acc[im][jn][kh * 2 + 1] * pi * s_tinv[c + 1];
                if (gc < NV) {
                    __stcs(orow + gc, v0);
                    if (v0 > bv) { bv = v0; bn = gc; }
                }
                if (gc + 1 < NV) {
                    __stcs(orow + gc + 1, v1);
                    if (v1 > bv) { bv = v1; bn = gc + 1; }
                }
            }
            if (doArgmax) {
                unsigned long long key = (bn >= 0) ? packKey(bv, bn) : 0ull;
                unsigned long long o1 = __shfl_xor_sync(0xffffffffu, key, 1);
                if (o1 > key) key = o1;
                unsigned long long o2 = __shfl_xor_sync(0xffffffffu, key, 2);
                if (o2 > key) key = o2;
                if ((lane & 3) == 0 && key)
                    atomicMax(&d_best[row0 + r], key);
            }
        }
    }
}

// ---------------- K4: decode fused argmax ---------------------------------
__global__ void k_decode(float* __restrict__ nnOut) {
    int t = blockIdx.x * blockDim.x + threadIdx.x;
    if (t < NTOK) nnOut[t] = (float)(~(unsigned)(d_best[t] & 0xFFFFFFFFull));
}

// ---------------- launch ---------------------------------------------------
extern "C" void kernel_launch(void* const* d_in, const int* in_sizes, int n_in,
                              void* d_out, int out_size) {
    const int* utt = (const int*)d_in[0];     // [B,S] int32
    const float* emb = (const float*)d_in[1]; // [V,E] fp32
    const float* grad = (const float*)d_in[2];// [B,S,E] fp32
    float* out = (float*)d_out;

    float* nnOut = nullptr;
    float* simOut = out;
    if (out_size == NTOK * (NV + 1)) {        // tuple order: nn_idx, then sim
        nnOut = out;
        simOut = out + NTOK;
    }

    k_prep<<<NVP + NB, 128>>>(emb, grad);
    k_perturb<<<NTOK, 128>>>(utt, emb, grad);

    const int dynSmem = 2 * STG_BYTES;        // 64KB
    static int attrSet = 0;
    if (!attrSet) {
        cudaFuncSetAttribute(k_gemm, cudaFuncAttributeMaxDynamicSharedMemorySize, dynSmem);
        attrSet = 1;
    }
    dim3 g(NBLK, NTOK / TC_M);
    k_gemm<<<g, 256, dynSmem>>>(simOut, nnOut != nullptr);

    if (nnOut) k_decode<<<(NTOK + 255) / 256, 256>>>(nnOut);
}